// round 17
// baseline (speedup 1.0000x reference)
#include <cuda_runtime.h>
#include <cuda_bf16.h>
#include <cuda_fp16.h>
#include <cstdint>
#include <math.h>

#define NB   8
#define NC   256
#define NPIX 4096
#define DQK  32

// ---------------- scratch (device globals; no allocation allowed) ----------------
// Q images: [b][qtile(32)] 16KB pre-swizzled: 128 rows x 128B, row = qhi(32 bf16)|qlo(32 bf16)
__device__ __align__(16) unsigned char g_q[NB * 32 * 16384];
// KV images: [b][ktile(64)] 40KB = K 8KB (64 rows x 128B, khi|klo bf16) | V 32KB (fp16)
//   V region layout: off(key,c) = key*512 + ((((c)>>3) ^ (key&7))<<4) + ((c)&7)*2
__device__ __align__(16) unsigned char g_kv[NB * 64 * 40960];
__device__ float g_psum[NC * 256];                        // [c][cta]
__device__ float g_psq [NC * 256];
__device__ float g_sa[NC];
__device__ float g_sb[NC];

// ---------------- PTX helpers ----------------
__device__ __forceinline__ uint32_t smem_u32(const void* p) {
    return (uint32_t)__cvta_generic_to_shared(p);
}
__device__ __forceinline__ uint64_t gptr(const void* p) {
    uint64_t r; asm("cvta.to.global.u64 %0, %1;" : "=l"(r) : "l"(p)); return r;
}
#define SWZ(o) ((o) ^ (((o) >> 3) & 0x70))

__device__ __forceinline__ void ldsm_x4(uint32_t* a, uint32_t addr) {
    asm volatile("ldmatrix.sync.aligned.m8n8.x4.shared.b16 {%0,%1,%2,%3}, [%4];"
        : "=r"(a[0]), "=r"(a[1]), "=r"(a[2]), "=r"(a[3]) : "r"(addr));
}
__device__ __forceinline__ void ldsm_x4_t(uint32_t* a, uint32_t addr) {
    asm volatile("ldmatrix.sync.aligned.m8n8.x4.trans.shared.b16 {%0,%1,%2,%3}, [%4];"
        : "=r"(a[0]), "=r"(a[1]), "=r"(a[2]), "=r"(a[3]) : "r"(addr));
}
__device__ __forceinline__ void mma16816(float* d, const uint32_t* a, const uint32_t* b) {
    asm volatile("mma.sync.aligned.m16n8k16.row.col.f32.bf16.bf16.f32 "
        "{%0,%1,%2,%3},{%4,%5,%6,%7},{%8,%9},{%0,%1,%2,%3};"
        : "+f"(d[0]), "+f"(d[1]), "+f"(d[2]), "+f"(d[3])
        : "r"(a[0]), "r"(a[1]), "r"(a[2]), "r"(a[3]), "r"(b[0]), "r"(b[1]));
}
__device__ __forceinline__ void mma16816h(float* d, const uint32_t* a, const uint32_t* b) {
    asm volatile("mma.sync.aligned.m16n8k16.row.col.f32.f16.f16.f32 "
        "{%0,%1,%2,%3},{%4,%5,%6,%7},{%8,%9},{%0,%1,%2,%3};"
        : "+f"(d[0]), "+f"(d[1]), "+f"(d[2]), "+f"(d[3])
        : "r"(a[0]), "r"(a[1]), "r"(a[2]), "r"(a[3]), "r"(b[0]), "r"(b[1]));
}
#define MBAR_INIT_N(a, n) \
    asm volatile("mbarrier.init.shared.b64 [%0], %1;" :: "r"(a), "r"(n) : "memory")
#define MBAR_ARRIVE(a) \
    asm volatile("mbarrier.arrive.shared.b64 _, [%0];" :: "r"(a) : "memory")
#define MBAR_EXPECT(a, bytes) \
    asm volatile("mbarrier.arrive.expect_tx.shared.b64 _, [%0], %1;" :: "r"(a), "r"(bytes) : "memory")
#define BULK_G2S(dst, src, bytes, mbar) \
    asm volatile("cp.async.bulk.shared::cluster.global.mbarrier::complete_tx::bytes [%0], [%1], %2, [%3];" \
        :: "r"(dst), "l"(src), "r"(bytes), "r"(mbar) : "memory")

__device__ __forceinline__ void mbar_wait(uint32_t addr, uint32_t phase) {
    asm volatile(
        "{\n\t.reg .pred P;\n\t"
        "LW%=:\n\t"
        "mbarrier.try_wait.parity.acquire.cta.shared::cta.b64 P, [%0], %1, 0x989680;\n\t"
        "@!P bra LW%=;\n\t}"
        :: "r"(addr), "r"(phase) : "memory");
}

__device__ __forceinline__ void split2(__nv_bfloat162& h, __nv_bfloat162& lo, float a, float b) {
    h.x  = __float2bfloat16(a);
    h.y  = __float2bfloat16(b);
    lo.x = __float2bfloat16(a - __bfloat162float(h.x));
    lo.y = __float2bfloat16(b - __bfloat162float(h.y));
}

// ---------------- kernel 1: QKV projection on tensor cores (bf16 3-term split) ----------------
#define PJ_SXH   0
#define PJ_SXL   32768
#define PJ_SWH   65536
#define PJ_SWL   73728
#define PJ_STAGE 81920
#define PJ_SMEM  98304

__global__ void __launch_bounds__(256) proj_kernel(
    const float* __restrict__ x,
    const float* __restrict__ wq, const float* __restrict__ bq,
    const float* __restrict__ wk, const float* __restrict__ bk,
    const float* __restrict__ wv, const float* __restrict__ bv)
{
    extern __shared__ __align__(1024) unsigned char ps[];
    const uint32_t sb = smem_u32(ps);
    const int tid = threadIdx.x;
    const int w = tid >> 5, l = tid & 31;
    const int p0 = blockIdx.x * 64;
    const int b  = blockIdx.y;

    const float* xb = x + (size_t)b * NC * NPIX + p0;
    #pragma unroll
    for (int i = 0; i < 16; i++) {
        int idx4 = tid + i * 256;
        int c = idx4 >> 4, pl4 = (idx4 & 15) * 4;
        float4 v = *(const float4*)(xb + (size_t)c * NPIX + pl4);
        __nv_bfloat162 h0, l0, h1, l1;
        split2(h0, l0, v.x, v.y);
        split2(h1, l1, v.z, v.w);
        uint32_t o1 = SWZ((uint32_t)c * 128 + pl4 * 2);
        uint32_t o2 = SWZ((uint32_t)c * 128 + pl4 * 2 + 4);
        *(__nv_bfloat162*)(ps + PJ_SXH + o1) = h0;
        *(__nv_bfloat162*)(ps + PJ_SXH + o2) = h1;
        *(__nv_bfloat162*)(ps + PJ_SXL + o1) = l0;
        *(__nv_bfloat162*)(ps + PJ_SXL + o2) = l1;
    }

    const int or0    = 16 * (w >> 1);
    const int pnb    = 32 * (w & 1);
    const int ar_l   = l & 15;
    const int ac8    = (l >> 4) * 8;
    const int xrow_l = ((l >> 3) & 1) * 8 + (l & 7);
    const int xcc8   = ((l >> 4) & 1) * 8;

    for (int ot = 0; ot < 5; ot++) {
        float acc[4][4];
        #pragma unroll
        for (int nt = 0; nt < 4; nt++)
            #pragma unroll
            for (int c = 0; c < 4; c++) acc[nt][c] = 0.f;

        for (int cb = 0; cb < 4; cb++) {
            #pragma unroll
            for (int i = 0; i < 4; i++) {
                int idx4 = tid + i * 256;
                int o = idx4 >> 4, cc4 = (idx4 & 15) * 4;
                const float* wrow;
                if (ot == 0) wrow = (o < 32) ? (wq + o * NC) : (wk + (o - 32) * NC);
                else         wrow = wv + ((ot - 1) * 64 + o) * NC;
                float4 v = *(const float4*)(wrow + cb * 64 + cc4);
                __nv_bfloat162 h0, l0, h1, l1;
                split2(h0, l0, v.x, v.y);
                split2(h1, l1, v.z, v.w);
                uint32_t o1 = SWZ((uint32_t)o * 128 + cc4 * 2);
                uint32_t o2 = SWZ((uint32_t)o * 128 + cc4 * 2 + 4);
                *(__nv_bfloat162*)(ps + PJ_SWH + o1) = h0;
                *(__nv_bfloat162*)(ps + PJ_SWH + o2) = h1;
                *(__nv_bfloat162*)(ps + PJ_SWL + o1) = l0;
                *(__nv_bfloat162*)(ps + PJ_SWL + o2) = l1;
            }
            __syncthreads();

            #pragma unroll
            for (int kk = 0; kk < 4; kk++) {
                uint32_t ah[4], al[4];
                uint32_t aoff = SWZ((uint32_t)(or0 + ar_l) * 128 + (kk * 16 + ac8) * 2);
                ldsm_x4(ah, sb + PJ_SWH + aoff);
                ldsm_x4(al, sb + PJ_SWL + aoff);
                #pragma unroll
                for (int nb2 = 0; nb2 < 2; nb2++) {
                    uint32_t bh[4], bl[4];
                    uint32_t xoff = SWZ((uint32_t)(cb * 64 + kk * 16 + xrow_l) * 128
                                        + (pnb + nb2 * 16 + xcc8) * 2);
                    ldsm_x4_t(bh, sb + PJ_SXH + xoff);
                    ldsm_x4_t(bl, sb + PJ_SXL + xoff);
                    float* a0 = acc[nb2 * 2];
                    float* a1 = acc[nb2 * 2 + 1];
                    mma16816(a0, ah, bh + 0); mma16816(a1, ah, bh + 2);
                    mma16816(a0, ah, bl + 0); mma16816(a1, ah, bl + 2);
                    mma16816(a0, al, bh + 0); mma16816(a1, al, bh + 2);
                }
            }
            __syncthreads();
        }

        const int rlo = or0 + (l >> 2);
        const int pc  = pnb + 2 * (l & 3);
        if (ot == 0) {
            #pragma unroll
            for (int nt = 0; nt < 4; nt++) {
                #pragma unroll
                for (int e = 0; e < 4; e++) {
                    int o    = rlo + (e >> 1) * 8;
                    int pixl = pc + nt * 8 + (e & 1);
                    float v2 = acc[nt][e] + ((o < 32) ? bq[o] : bk[o - 32]);
                    __nv_bfloat16 h  = __float2bfloat16(v2);
                    __nv_bfloat16 lo = __float2bfloat16(v2 - __bfloat162float(h));
                    int oc   = (o < 32) ? o : (o - 32);
                    int base = (o < 32) ? 0 : 8192;
                    *(__nv_bfloat16*)(ps + PJ_STAGE + base + SWZ((uint32_t)pixl * 128 + oc * 2)) = h;
                    *(__nv_bfloat16*)(ps + PJ_STAGE + base + SWZ((uint32_t)pixl * 128 + (oc + 32) * 2)) = lo;
                }
            }
            __syncthreads();
            size_t qdst = ((size_t)b * 32 + (p0 >> 7)) * 16384 + (size_t)(p0 & 127) * 128;
            size_t kdst = ((size_t)b * 64 + (p0 >> 6)) * 40960;
            const uint4* st = (const uint4*)(ps + PJ_STAGE);
            #pragma unroll
            for (int it = 0; it < 2; it++) {
                int idx = tid + it * 256;
                *(uint4*)(g_q  + qdst + (size_t)idx * 16) = st[idx];
                *(uint4*)(g_kv + kdst + (size_t)idx * 16) = st[512 + idx];
            }
            __syncthreads();
        } else {
            int c0v = (ot - 1) * 64;
            #pragma unroll
            for (int nt = 0; nt < 4; nt++) {
                #pragma unroll
                for (int e = 0; e < 4; e++) {
                    int cl   = rlo + (e >> 1) * 8;
                    int srow = pc + nt * 8 + (e & 1);
                    float v2 = acc[nt][e] + bv[c0v + cl];
                    uint32_t off = (uint32_t)srow * 128
                                 + ((((uint32_t)cl >> 3) ^ (srow & 7)) << 4) + (cl & 7) * 2;
                    *(__half*)(ps + PJ_STAGE + off) = __float2half_rn(v2);
                }
            }
            __syncthreads();
            size_t vdst = ((size_t)b * 64 + (p0 >> 6)) * 40960 + 8192 + (size_t)(c0v >> 3) * 16;
            const uint4* st = (const uint4*)(ps + PJ_STAGE);
            #pragma unroll
            for (int it = 0; it < 2; it++) {
                int idx = tid + it * 256;
                int key = idx >> 3, chk = idx & 7;
                *(uint4*)(g_kv + vdst + (size_t)key * 512 + chk * 16) = st[idx];
            }
            __syncthreads();
        }
    }
}

// ---------------- kernel 2: flash attention + fused residual/BN-partial epilogue ----------------
// 3-stage KV ring (full/empty mbarriers, no per-tile syncthreads).
// Epilogue: O -> smem [c][pix] transpose -> y = gamma*o + x (coalesced NCHW) + partials.
#define STG      40960
#define OFF_S0   16384
#define OFF_MB   139264      // full[0..2] at +0/8/16, empty[0..2] at +24/32/40
#define FL_SMEM  139312
#define OROW     132         // f32 per O-stage row (128 + 4 pad)

__global__ void __launch_bounds__(512, 1) flash_kernel(
    const float* __restrict__ x, const float* __restrict__ gamma,
    float* __restrict__ y)
{
    extern __shared__ __align__(1024) char sm[];
    const uint32_t sbase = smem_u32(sm);
    const int tid = threadIdx.x;
    const int w = tid >> 5, l = tid & 31;
    const int rg = w >> 1;
    const int ch = w & 1;
    const int b  = blockIdx.y;
    const int i0 = blockIdx.x * 128;

    const uint32_t mbF = sbase + OFF_MB;
    const uint32_t mbE = sbase + OFF_MB + 24;
    if (tid == 0) {
        #pragma unroll
        for (int s = 0; s < 3; s++) {
            MBAR_INIT_N(mbF + s * 8, 1);
            MBAR_INIT_N(mbE + s * 8, 16);
        }
        asm volatile("fence.proxy.async.shared::cta;" ::: "memory");
    }
    __syncthreads();

    const uint64_t gkv = gptr(g_kv) + (size_t)b * 64 * STG;
    if (tid == 0) {
        uint64_t gq = gptr(g_q) + ((size_t)b * 32 + blockIdx.x) * 16384;
        MBAR_EXPECT(mbF, 16384u + (uint32_t)STG);
        BULK_G2S(sbase, gq, 16384u, mbF);
        BULK_G2S(sbase + OFF_S0, gkv, (uint32_t)STG, mbF);
        MBAR_EXPECT(mbF + 8, (uint32_t)STG);
        BULK_G2S(sbase + OFF_S0 + STG, gkv + STG, (uint32_t)STG, mbF + 8);
        MBAR_EXPECT(mbF + 16, (uint32_t)STG);
        BULK_G2S(sbase + OFF_S0 + 2 * STG, gkv + 2 * STG, (uint32_t)STG, mbF + 16);
    }

    // stage 0 carries Q too — wait it, hoist Q fragments
    mbar_wait(mbF, 0);
    const int qrow = rg * 16 + (l & 15);
    const int qc8  = (l >> 4) * 8;
    uint32_t qh[2][4], ql[2][4];
    #pragma unroll
    for (int kk = 0; kk < 2; kk++) {
        ldsm_x4(qh[kk], sbase + SWZ(qrow * 128 + (kk * 16 + qc8) * 2));
        ldsm_x4(ql[kk], sbase + SWZ(qrow * 128 + (kk * 16 + 32 + qc8) * 2));
    }

    float o_[16][4];
    #pragma unroll
    for (int nt = 0; nt < 16; nt++)
        #pragma unroll
        for (int c = 0; c < 4; c++) o_[nt][c] = 0.f;
    float sum0 = 0.f, sum1 = 0.f;
    float m0 = -1e30f, m1 = -1e30f;

    const int krow_l = ((l >> 4) & 1) * 8 + (l & 7);
    const int kc8    = ((l >> 3) & 1) * 8;
    const int vkey_l = ((l >> 3) & 1) * 8 + (l & 7);
    const int vcc_l  = ch * 16 + ((l >> 4) & 1);

    for (int t = 0; t < 64; t++) {
        const int s = t - (t / 3) * 3;
        const int u = t / 3;
        const uint32_t sK = sbase + OFF_S0 + (uint32_t)s * STG;
        const uint32_t fb = mbF + s * 8;
        const uint32_t eb = mbE + s * 8;
        mbar_wait(fb, u & 1);

        #pragma unroll
        for (int half = 0; half < 2; half++) {
            float s_[2][8];
            #pragma unroll
            for (int kg2 = 0; kg2 < 2; kg2++) {
                int kg = half * 2 + kg2;
                float* se = &s_[kg2][0];
                float* so = &s_[kg2][4];
                se[0] = se[1] = se[2] = se[3] = 0.f;
                so[0] = so[1] = so[2] = so[3] = 0.f;
                #pragma unroll
                for (int kk = 0; kk < 2; kk++) {
                    uint32_t kf[4];
                    ldsm_x4(kf, sK + SWZ((kg * 16 + krow_l) * 128 + (kk * 16 + kc8) * 2));
                    mma16816(se, qh[kk], kf + 0);
                    mma16816(so, qh[kk], kf + 2);
                    mma16816(se, ql[kk], kf + 0);
                    mma16816(so, ql[kk], kf + 2);
                    ldsm_x4(kf, sK + SWZ((kg * 16 + krow_l) * 128 + (kk * 16 + 32 + kc8) * 2));
                    mma16816(se, qh[kk], kf + 0);
                    mma16816(so, qh[kk], kf + 2);
                }
            }
            float mt0 = fmaxf(fmaxf(fmaxf(s_[0][0], s_[0][1]), fmaxf(s_[0][4], s_[0][5])),
                              fmaxf(fmaxf(s_[1][0], s_[1][1]), fmaxf(s_[1][4], s_[1][5])));
            float mt1 = fmaxf(fmaxf(fmaxf(s_[0][2], s_[0][3]), fmaxf(s_[0][6], s_[0][7])),
                              fmaxf(fmaxf(s_[1][2], s_[1][3]), fmaxf(s_[1][6], s_[1][7])));
            mt0 = fmaxf(mt0, __shfl_xor_sync(0xffffffffu, mt0, 1));
            mt0 = fmaxf(mt0, __shfl_xor_sync(0xffffffffu, mt0, 2));
            mt1 = fmaxf(mt1, __shfl_xor_sync(0xffffffffu, mt1, 1));
            mt1 = fmaxf(mt1, __shfl_xor_sync(0xffffffffu, mt1, 2));
            if (mt0 > m0) {
                float sc = __expf(m0 - mt0);
                sum0 *= sc;
                #pragma unroll
                for (int nt = 0; nt < 16; nt++) { o_[nt][0] *= sc; o_[nt][1] *= sc; }
                m0 = mt0;
            }
            if (mt1 > m1) {
                float sc = __expf(m1 - mt1);
                sum1 *= sc;
                #pragma unroll
                for (int nt = 0; nt < 16; nt++) { o_[nt][2] *= sc; o_[nt][3] *= sc; }
                m1 = mt1;
            }
            #pragma unroll
            for (int kg2 = 0; kg2 < 2; kg2++) {
                int kg = half * 2 + kg2;
                float pe0 = __expf(s_[kg2][0] - m0), pe1 = __expf(s_[kg2][1] - m0);
                float pq0 = __expf(s_[kg2][2] - m1), pq1 = __expf(s_[kg2][3] - m1);
                float pe2 = __expf(s_[kg2][4] - m0), pe3 = __expf(s_[kg2][5] - m0);
                float pq2 = __expf(s_[kg2][6] - m1), pq3 = __expf(s_[kg2][7] - m1);
                sum0 += (pe0 + pe1) + (pe2 + pe3);
                sum1 += (pq0 + pq1) + (pq2 + pq3);
                uint32_t pf[4];
                __half2 h0 = __floats2half2_rn(pe0, pe1); pf[0] = *(uint32_t*)&h0;
                __half2 h1 = __floats2half2_rn(pq0, pq1); pf[1] = *(uint32_t*)&h1;
                __half2 h2 = __floats2half2_rn(pe2, pe3); pf[2] = *(uint32_t*)&h2;
                __half2 h3 = __floats2half2_rn(pq2, pq3); pf[3] = *(uint32_t*)&h3;

                const int key = kg * 16 + vkey_l;
                const uint32_t rowb = sK + 8192 + ((uint32_t)key << 9);
                const int kx = key & 7;
                #pragma unroll
                for (int ntp = 0; ntp < 8; ntp++) {
                    const int cc = vcc_l + ntp * 2;
                    uint32_t v[4];
                    ldsm_x4_t(v, rowb + (uint32_t)((cc ^ kx) << 4));
                    mma16816h(o_[2 * ntp],     pf, v + 0);
                    mma16816h(o_[2 * ntp + 1], pf, v + 2);
                }
            }
        }

        // consumer arrive (1 per warp); producer refills this stage for tile t+3
        if (l == 0) MBAR_ARRIVE(eb);
        if (tid == 0 && t < 61) {
            mbar_wait(eb, u & 1);          // all 16 warps done with this stage
            MBAR_EXPECT(fb, (uint32_t)STG);
            BULK_G2S(sK, gkv + (size_t)(t + 3) * STG, (uint32_t)STG, fb);
        }
    }

    // ---- epilogue: normalize, transpose to smem [c][pix], fused residual + partials ----
    sum0 += __shfl_xor_sync(0xffffffffu, sum0, 1);
    sum0 += __shfl_xor_sync(0xffffffffu, sum0, 2);
    sum1 += __shfl_xor_sync(0xffffffffu, sum1, 1);
    sum1 += __shfl_xor_sync(0xffffffffu, sum1, 2);
    float inv0 = 1.0f / sum0, inv1 = 1.0f / sum1;

    __syncthreads();    // all stage reads done; safe to reuse smem
    float* ost = (float*)sm;                 // [256][OROW]
    const int prow = rg * 16 + (l >> 2);
    const int ccol = ch * 128 + 2 * (l & 3);
    #pragma unroll
    for (int nt = 0; nt < 16; nt++) {
        int c = ccol + nt * 8;
        ost[(c    ) * OROW + prow    ] = o_[nt][0] * inv0;
        ost[(c + 1) * OROW + prow    ] = o_[nt][1] * inv0;
        ost[(c    ) * OROW + prow + 8] = o_[nt][2] * inv1;
        ost[(c + 1) * OROW + prow + 8] = o_[nt][3] * inv1;
    }
    __syncthreads();

    {
        const int c  = tid >> 1;
        const int hf = tid & 1;
        const float g = gamma[0];
        size_t gi = ((size_t)b * NC + c) * NPIX + i0 + hf * 64;
        const float* xr = x + gi;
        float* yr = y + gi;
        const float* row = ost + (size_t)c * OROW + hf * 64;
        float s = 0.f, s2 = 0.f;
        #pragma unroll
        for (int i = 0; i < 64; i += 4) {
            float4 ov = *(const float4*)(row + i);
            float4 xv = *(const float4*)(xr + i);
            float4 val;
            val.x = g * ov.x + xv.x;
            val.y = g * ov.y + xv.y;
            val.z = g * ov.z + xv.z;
            val.w = g * ov.w + xv.w;
            *(float4*)(yr + i) = val;
            s  += (val.x + val.y) + (val.z + val.w);
            s2 += (val.x * val.x + val.y * val.y) + (val.z * val.z + val.w * val.w);
        }
        s  += __shfl_xor_sync(0xffffffffu, s,  1);
        s2 += __shfl_xor_sync(0xffffffffu, s2, 1);
        if (hf == 0) {
            int cta = b * 32 + blockIdx.x;          // 0..255
            g_psum[(size_t)c * 256 + cta] = s;
            g_psq [(size_t)c * 256 + cta] = s2;
        }
    }
}

// ---------------- kernel 3: BN statistics ----------------
__global__ void stats_kernel(const float* __restrict__ bnw, const float* __restrict__ bnb)
{
    int c = blockIdx.x;
    int l = threadIdx.x;
    float s = 0.f, s2 = 0.f;
    for (int k = l; k < 256; k += 32) {
        s  += g_psum[(size_t)c * 256 + k];
        s2 += g_psq [(size_t)c * 256 + k];
    }
    #pragma unroll
    for (int off = 16; off; off >>= 1) {
        s  += __shfl_xor_sync(0xffffffffu, s,  off);
        s2 += __shfl_xor_sync(0xffffffffu, s2, off);
    }
    if (l == 0) {
        const float M = (float)(NB * NPIX);
        float mean = s / M;
        float var  = s2 / M - mean * mean;
        float inv  = rsqrtf(var + 1e-5f);
        float a = bnw[c] * inv;
        g_sa[c] = a;
        g_sb[c] = bnb[c] - mean * a;
    }
}

// ---------------- kernel 4: normalize + ReLU ----------------
__global__ void __launch_bounds__(256) norm_kernel(float* __restrict__ y)
{
    int idx = blockIdx.x * 256 + threadIdx.x;
    int c = (idx >> 10) & (NC - 1);
    float a = g_sa[c], bb = g_sb[c];
    float4* y4 = (float4*)y;
    float4 v = y4[idx];
    v.x = fmaxf(a * v.x + bb, 0.f);
    v.y = fmaxf(a * v.y + bb, 0.f);
    v.z = fmaxf(a * v.z + bb, 0.f);
    v.w = fmaxf(a * v.w + bb, 0.f);
    y4[idx] = v;
}

// ---------------- launch ----------------
extern "C" void kernel_launch(void* const* d_in, const int* in_sizes, int n_in,
                              void* d_out, int out_size)
{
    const float* x     = (const float*)d_in[0];
    const float* wq    = (const float*)d_in[1];
    const float* bq    = (const float*)d_in[2];
    const float* wk    = (const float*)d_in[3];
    const float* bk    = (const float*)d_in[4];
    const float* wv    = (const float*)d_in[5];
    const float* bv    = (const float*)d_in[6];
    const float* gamma = (const float*)d_in[7];
    const float* bnw   = (const float*)d_in[8];
    const float* bnb   = (const float*)d_in[9];
    float* out = (float*)d_out;

    cudaFuncSetAttribute(proj_kernel, cudaFuncAttributeMaxDynamicSharedMemorySize, PJ_SMEM);
    proj_kernel<<<dim3(NPIX / 64, NB), 256, PJ_SMEM>>>(x, wq, bq, wk, bk, wv, bv);

    cudaFuncSetAttribute(flash_kernel, cudaFuncAttributeMaxDynamicSharedMemorySize, FL_SMEM);
    flash_kernel<<<dim3(NPIX / 128, NB), 512, FL_SMEM>>>(x, gamma, out);

    stats_kernel<<<NC, 32>>>(bnw, bnb);
    norm_kernel<<<(NB * NC * NPIX / 4) / 256, 256>>>(out);
}